// round 7
// baseline (speedup 1.0000x reference)
#include <cuda_runtime.h>
#include <cuda_fp16.h>
#include <stdint.h>

// Problem constants (fixed shapes from reference)
#define M_DIM 32
#define N_DIM 11008
#define K_DIM 4096

// Harness promotes unsupported dtypes: float16 -> float32, int8 -> int32.
// So: x fp32 [32,4096], qweight int32 [11008,4096], scales fp32 [11008],
// bias fp32 [11008], out fp32 [32,11008] (values fp16-rounded like reference).

#define N_TILE   64                 // output channels per CTA (11008 = 172 * 64)
#define K_CHUNK  64                 // K elements staged per pipeline stage
#define N_WARPS  8
#define THREADS  (N_WARPS * 32)
#define N_CHUNKS (K_DIM / K_CHUNK)  // 64
#define KSTEPS   (K_CHUNK / 16)     // 4 mma k-steps per chunk

#define X_STRIDE 72                 // halves per x row in smem (64 + 8 pad)
#define W_STRIDE 72                 // int32 per w row in smem (64 + 8 pad -> conflict-free LDS.64)

// fp16 copy of x, produced by a pre-kernel each launch (deterministic).
__device__ __half g_x16[M_DIM * K_DIM];   // 256 KB static

__device__ __forceinline__ uint32_t smem_addr(const void* p) {
    return (uint32_t)__cvta_generic_to_shared(p);
}

__global__ void convert_x_kernel(const float* __restrict__ x32) {
    int i = blockIdx.x * blockDim.x + threadIdx.x;   // grid covers exactly 131072
    g_x16[i] = __float2half(x32[i]);                 // exact: values are fp16-representable
}

// Stage K-chunk `k0`: x (fp16 from g_x16) and weights (raw int32) into smem buffers.
__device__ __forceinline__ void issue_chunk(
    const int32_t* __restrict__ qw, int n_base,
    __half* sx, int32_t* sw, int k0, int tid)
{
    // x chunk: 32 rows x 64 halves = 128 B/row = 8 segs of 16 B -> 256 segs, 1 per thread
    {
        int row = tid >> 3;
        int col = tid & 7;
        const __half* src = g_x16 + (size_t)row * K_DIM + k0 + col * 8;
        uint32_t dst = smem_addr(sx + row * X_STRIDE + col * 8);
        asm volatile("cp.async.cg.shared.global [%0], [%1], 16;\n" :: "r"(dst), "l"(src));
    }
    // w chunk: 64 rows x 64 int32 = 256 B/row = 16 segs of 16 B -> 1024 segs, 4 per thread
    #pragma unroll
    for (int s = 0; s < 4; s++) {
        int seg = tid + s * THREADS;
        int row = seg >> 4;
        int col = seg & 15;
        const int32_t* src = qw + (size_t)(n_base + row) * K_DIM + k0 + col * 4;
        uint32_t dst = smem_addr(sw + row * W_STRIDE + col * 4);
        asm volatile("cp.async.cg.shared.global [%0], [%1], 16;\n" :: "r"(dst), "l"(src));
    }
    asm volatile("cp.async.commit_group;\n");
}

__global__ void __launch_bounds__(THREADS, 2)
qlinear_s8_kernel(const int32_t* __restrict__ qw,
                  const float* __restrict__ scales,
                  const float* __restrict__ bias,
                  float* __restrict__ out)
{
    __shared__ __align__(16) __half   sx[2][M_DIM * X_STRIDE];   // 2 x 4608 B
    __shared__ __align__(16) int32_t  sw[2][N_TILE * W_STRIDE];  // 2 x 18432 B

    const int tid  = threadIdx.x;
    const int warp = tid >> 5;
    const int lane = tid & 31;
    const int n_base = blockIdx.x * N_TILE;

    float acc[2][4] = {{0.f, 0.f, 0.f, 0.f}, {0.f, 0.f, 0.f, 0.f}};

    // B operand per-thread source: row (n) = warp*8 + lane/4, k offset (lane%4)*2.
    const int o_row = warp * 8 + (lane >> 2);
    const int kb    = (lane & 3) * 2;

    issue_chunk(qw, n_base, sx[0], sw[0], 0, tid);

    for (int ch = 0; ch < N_CHUNKS; ch++) {
        const int buf = ch & 1;
        if (ch + 1 < N_CHUNKS) {
            issue_chunk(qw, n_base, sx[buf ^ 1], sw[buf ^ 1], (ch + 1) * K_CHUNK, tid);
            asm volatile("cp.async.wait_group 1;\n");
        } else {
            asm volatile("cp.async.wait_group 0;\n");
        }
        __syncthreads();

        const __half*   xs = sx[buf];
        const int32_t*  ws = &sw[buf][o_row * W_STRIDE + kb];

        // ldmatrix base: lane -> row (lane%16), col block (lane/16)*8 halves.
        const uint32_t a_base = smem_addr(xs) +
            ((uint32_t)((lane & 15) * X_STRIDE + (lane >> 4) * 8) * 2u);

        #pragma unroll
        for (int ks = 0; ks < KSTEPS; ks++) {
            const int kl = ks * 16;

            // A fragments: 2 m-tiles (rows 0-15, 16-31) via ldmatrix.x4
            uint32_t a0[4], a1[4];
            {
                uint32_t addr0 = a_base + (uint32_t)(kl * 2);
                asm volatile("ldmatrix.sync.aligned.m8n8.x4.shared.b16 {%0,%1,%2,%3}, [%4];\n"
                             : "=r"(a0[0]), "=r"(a0[1]), "=r"(a0[2]), "=r"(a0[3]) : "r"(addr0));
                uint32_t addr1 = addr0 + (uint32_t)(16 * X_STRIDE * 2);
                asm volatile("ldmatrix.sync.aligned.m8n8.x4.shared.b16 {%0,%1,%2,%3}, [%4];\n"
                             : "=r"(a1[0]), "=r"(a1[1]), "=r"(a1[2]), "=r"(a1[3]) : "r"(addr1));
            }

            // B fragment: int32 weight pairs -> half2 (exact for |v| <= 128)
            int2 w0 = *reinterpret_cast<const int2*>(ws + kl);       // k = kl+kb, kl+kb+1
            int2 w1 = *reinterpret_cast<const int2*>(ws + kl + 8);   // k = kl+8+kb, +1
            __half2 b0h = __halves2half2(__int2half_rn(w0.x), __int2half_rn(w0.y));
            __half2 b1h = __halves2half2(__int2half_rn(w1.x), __int2half_rn(w1.y));
            uint32_t b0 = *reinterpret_cast<uint32_t*>(&b0h);
            uint32_t b1 = *reinterpret_cast<uint32_t*>(&b1h);

            asm volatile(
                "mma.sync.aligned.m16n8k16.row.col.f32.f16.f16.f32 "
                "{%0,%1,%2,%3}, {%4,%5,%6,%7}, {%8,%9}, {%0,%1,%2,%3};\n"
                : "+f"(acc[0][0]), "+f"(acc[0][1]), "+f"(acc[0][2]), "+f"(acc[0][3])
                : "r"(a0[0]), "r"(a0[1]), "r"(a0[2]), "r"(a0[3]), "r"(b0), "r"(b1));
            asm volatile(
                "mma.sync.aligned.m16n8k16.row.col.f32.f16.f16.f32 "
                "{%0,%1,%2,%3}, {%4,%5,%6,%7}, {%8,%9}, {%0,%1,%2,%3};\n"
                : "+f"(acc[1][0]), "+f"(acc[1][1]), "+f"(acc[1][2]), "+f"(acc[1][3])
                : "r"(a1[0]), "r"(a1[1]), "r"(a1[2]), "r"(a1[3]), "r"(b0), "r"(b1));
        }
        __syncthreads();
    }

    // Epilogue: out[t][o] = fp16_round(acc * scale[o] + bias[o]), stored as fp32.
    // C fragment: rows lane/4 (+8), cols (lane%4)*2 (+1).
    const int oc = n_base + warp * 8 + (lane & 3) * 2;
    const float s0  = __ldg(scales + oc);
    const float s1  = __ldg(scales + oc + 1);
    const float bz0 = __ldg(bias + oc);
    const float bz1 = __ldg(bias + oc + 1);

    #pragma unroll
    for (int mt = 0; mt < 2; mt++) {
        const int t0 = mt * 16 + (lane >> 2);
        float2 v0, v1;
        v0.x = __half2float(__float2half(acc[mt][0] * s0 + bz0));
        v0.y = __half2float(__float2half(acc[mt][1] * s1 + bz1));
        v1.x = __half2float(__float2half(acc[mt][2] * s0 + bz0));
        v1.y = __half2float(__float2half(acc[mt][3] * s1 + bz1));
        *reinterpret_cast<float2*>(out + (size_t)t0 * N_DIM + oc)       = v0;
        *reinterpret_cast<float2*>(out + (size_t)(t0 + 8) * N_DIM + oc) = v1;
    }
}

extern "C" void kernel_launch(void* const* d_in, const int* in_sizes, int n_in,
                              void* d_out, int out_size)
{
    const float*    x      = (const float*)d_in[0];
    const int32_t*  qw     = (const int32_t*)d_in[1];
    const float*    scales = (const float*)d_in[2];
    const float*    bias   = (const float*)d_in[3];
    float*          out    = (float*)d_out;

    convert_x_kernel<<<(M_DIM * K_DIM) / THREADS, THREADS>>>(x);   // 512 blocks

    dim3 grid(N_DIM / N_TILE);   // 172
    dim3 block(THREADS);         // 256
    qlinear_s8_kernel<<<grid, block>>>(qw, scales, bias, out);
}

// round 8
// speedup vs baseline: 1.2214x; 1.2214x over previous
#include <cuda_runtime.h>
#include <cuda_fp16.h>
#include <stdint.h>

// Problem constants (fixed shapes from reference)
#define M_DIM 32
#define N_DIM 11008
#define K_DIM 4096

// Harness promotes unsupported dtypes: float16 -> float32, int8 -> int32.
// x fp32 [32,4096], qweight int32 [11008,4096], scales fp32 [11008],
// bias fp32 [11008], out fp32 [32,11008] (values fp16-rounded like reference).

#define N_TILE   64                 // output channels per CTA (11008 = 172 * 64)
#define SPLIT_K  4                  // K-splits -> grid (172, 4) = 688 CTAs
#define K_PER_SPLIT (K_DIM / SPLIT_K)      // 1024
#define K_CHUNK  64                 // K elements staged per pipeline stage
#define N_WARPS  8
#define THREADS  (N_WARPS * 32)
#define N_CHUNKS (K_PER_SPLIT / K_CHUNK)   // 16
#define KSTEPS   (K_CHUNK / 16)     // 4 mma k-steps per chunk

#define X_STRIDE 72                 // halves per x row in smem (64 + 8 pad)
#define W_STRIDE 72                 // int32 per w row in smem (64 + 8 pad)

#define MN (M_DIM * N_DIM)          // 352256

// fp16 copy of x (pre-kernel), and fp32 split-K partials. Static device scratch.
__device__ __half g_x16[M_DIM * K_DIM];          // 256 KB
__device__ float  g_part[SPLIT_K * MN];          // 5.64 MB

__device__ __forceinline__ uint32_t smem_addr(const void* p) {
    return (uint32_t)__cvta_generic_to_shared(p);
}

__global__ void convert_x_kernel(const float* __restrict__ x32) {
    int i = blockIdx.x * blockDim.x + threadIdx.x;   // covers exactly 131072
    g_x16[i] = __float2half(x32[i]);                 // exact
}

// Stage K-chunk `k0`: x (fp16) and weights (raw int32) into smem buffers.
__device__ __forceinline__ void issue_chunk(
    const int32_t* __restrict__ qw, int n_base,
    __half* sx, int32_t* sw, int k0, int tid)
{
    // w chunk first (the critical stream): 64 rows x 64 int32 = 16 segs/row of 16 B
    #pragma unroll
    for (int s = 0; s < 4; s++) {
        int seg = tid + s * THREADS;
        int row = seg >> 4;
        int col = seg & 15;
        const int32_t* src = qw + (size_t)(n_base + row) * K_DIM + k0 + col * 4;
        uint32_t dst = smem_addr(sw + row * W_STRIDE + col * 4);
        asm volatile("cp.async.cg.shared.global [%0], [%1], 16;\n" :: "r"(dst), "l"(src));
    }
    // x chunk: 32 rows x 64 halves = 8 segs/row of 16 B -> 256 segs, 1 per thread
    {
        int row = tid >> 3;
        int col = tid & 7;
        const __half* src = g_x16 + (size_t)row * K_DIM + k0 + col * 8;
        uint32_t dst = smem_addr(sx + row * X_STRIDE + col * 8);
        asm volatile("cp.async.cg.shared.global [%0], [%1], 16;\n" :: "r"(dst), "l"(src));
    }
    asm volatile("cp.async.commit_group;\n");
}

__global__ void __launch_bounds__(THREADS, 2)
qlinear_s8_kernel(const int32_t* __restrict__ qw)
{
    __shared__ __align__(16) __half   sx[2][M_DIM * X_STRIDE];   // 2 x 4608 B
    __shared__ __align__(16) int32_t  sw[2][N_TILE * W_STRIDE];  // 2 x 18432 B

    const int tid  = threadIdx.x;
    const int warp = tid >> 5;
    const int lane = tid & 31;
    const int n_base  = blockIdx.x * N_TILE;
    const int split   = blockIdx.y;
    const int k_base  = split * K_PER_SPLIT;

    float acc[2][4] = {{0.f, 0.f, 0.f, 0.f}, {0.f, 0.f, 0.f, 0.f}};

    // B operand per-thread source: row (n) = warp*8 + lane/4, k offset (lane%4)*2.
    const int o_row = warp * 8 + (lane >> 2);
    const int kb    = (lane & 3) * 2;

    issue_chunk(qw, n_base, sx[0], sw[0], k_base, tid);

    for (int ch = 0; ch < N_CHUNKS; ch++) {
        const int buf = ch & 1;
        if (ch + 1 < N_CHUNKS) {
            issue_chunk(qw, n_base, sx[buf ^ 1], sw[buf ^ 1], k_base + (ch + 1) * K_CHUNK, tid);
            asm volatile("cp.async.wait_group 1;\n");
        } else {
            asm volatile("cp.async.wait_group 0;\n");
        }
        __syncthreads();

        const __half*   xs = sx[buf];
        const int32_t*  ws = &sw[buf][o_row * W_STRIDE + kb];

        // ldmatrix base: lane -> row (lane%16), col block (lane/16)*8 halves.
        const uint32_t a_base = smem_addr(xs) +
            ((uint32_t)((lane & 15) * X_STRIDE + (lane >> 4) * 8) * 2u);

        #pragma unroll
        for (int ks = 0; ks < KSTEPS; ks++) {
            const int kl = ks * 16;

            // A fragments: 2 m-tiles (rows 0-15, 16-31) via ldmatrix.x4
            uint32_t a0[4], a1[4];
            {
                uint32_t addr0 = a_base + (uint32_t)(kl * 2);
                asm volatile("ldmatrix.sync.aligned.m8n8.x4.shared.b16 {%0,%1,%2,%3}, [%4];\n"
                             : "=r"(a0[0]), "=r"(a0[1]), "=r"(a0[2]), "=r"(a0[3]) : "r"(addr0));
                uint32_t addr1 = addr0 + (uint32_t)(16 * X_STRIDE * 2);
                asm volatile("ldmatrix.sync.aligned.m8n8.x4.shared.b16 {%0,%1,%2,%3}, [%4];\n"
                             : "=r"(a1[0]), "=r"(a1[1]), "=r"(a1[2]), "=r"(a1[3]) : "r"(addr1));
            }

            // B fragment: int32 weight pairs -> half2 (exact for |v| <= 128)
            int2 w0 = *reinterpret_cast<const int2*>(ws + kl);
            int2 w1 = *reinterpret_cast<const int2*>(ws + kl + 8);
            __half2 b0h = __halves2half2(__int2half_rn(w0.x), __int2half_rn(w0.y));
            __half2 b1h = __halves2half2(__int2half_rn(w1.x), __int2half_rn(w1.y));
            uint32_t b0 = *reinterpret_cast<uint32_t*>(&b0h);
            uint32_t b1 = *reinterpret_cast<uint32_t*>(&b1h);

            asm volatile(
                "mma.sync.aligned.m16n8k16.row.col.f32.f16.f16.f32 "
                "{%0,%1,%2,%3}, {%4,%5,%6,%7}, {%8,%9}, {%0,%1,%2,%3};\n"
                : "+f"(acc[0][0]), "+f"(acc[0][1]), "+f"(acc[0][2]), "+f"(acc[0][3])
                : "r"(a0[0]), "r"(a0[1]), "r"(a0[2]), "r"(a0[3]), "r"(b0), "r"(b1));
            asm volatile(
                "mma.sync.aligned.m16n8k16.row.col.f32.f16.f16.f32 "
                "{%0,%1,%2,%3}, {%4,%5,%6,%7}, {%8,%9}, {%0,%1,%2,%3};\n"
                : "+f"(acc[1][0]), "+f"(acc[1][1]), "+f"(acc[1][2]), "+f"(acc[1][3])
                : "r"(a1[0]), "r"(a1[1]), "r"(a1[2]), "r"(a1[3]), "r"(b0), "r"(b1));
        }
        __syncthreads();
    }

    // Store raw fp32 partials (scale/bias applied in combine kernel).
    // C fragment: rows lane/4 (+8), cols (lane%4)*2 (+1).
    float* pbase = g_part + (size_t)split * MN;
    const int oc = n_base + warp * 8 + (lane & 3) * 2;

    #pragma unroll
    for (int mt = 0; mt < 2; mt++) {
        const int t0 = mt * 16 + (lane >> 2);
        *reinterpret_cast<float2*>(pbase + (size_t)t0 * N_DIM + oc) =
            make_float2(acc[mt][0], acc[mt][1]);
        *reinterpret_cast<float2*>(pbase + (size_t)(t0 + 8) * N_DIM + oc) =
            make_float2(acc[mt][2], acc[mt][3]);
    }
}

// Combine: out[t,o] = fp16_round((sum_s part[s,t,o]) * scale[o] + bias[o]) as fp32.
__global__ void __launch_bounds__(THREADS)
combine_kernel(const float* __restrict__ scales,
               const float* __restrict__ bias,
               float* __restrict__ out)
{
    const int i = (blockIdx.x * THREADS + threadIdx.x) * 4;   // element t*N+o, o % 4 == 0
    const int o = i % N_DIM;

    float4 p = *reinterpret_cast<const float4*>(g_part + i);
    #pragma unroll
    for (int s = 1; s < SPLIT_K; s++) {
        float4 q = *reinterpret_cast<const float4*>(g_part + (size_t)s * MN + i);
        p.x += q.x; p.y += q.y; p.z += q.z; p.w += q.w;
    }
    float4 sc = *reinterpret_cast<const float4*>(scales + o);
    float4 bz = *reinterpret_cast<const float4*>(bias + o);

    float4 v;
    v.x = __half2float(__float2half(p.x * sc.x + bz.x));
    v.y = __half2float(__float2half(p.y * sc.y + bz.y));
    v.z = __half2float(__float2half(p.z * sc.z + bz.z));
    v.w = __half2float(__float2half(p.w * sc.w + bz.w));
    *reinterpret_cast<float4*>(out + i) = v;
}

extern "C" void kernel_launch(void* const* d_in, const int* in_sizes, int n_in,
                              void* d_out, int out_size)
{
    const float*    x      = (const float*)d_in[0];
    const int32_t*  qw     = (const int32_t*)d_in[1];
    const float*    scales = (const float*)d_in[2];
    const float*    bias   = (const float*)d_in[3];
    float*          out    = (float*)d_out;

    convert_x_kernel<<<(M_DIM * K_DIM) / THREADS, THREADS>>>(x);   // 512 blocks

    dim3 grid(N_DIM / N_TILE, SPLIT_K);   // (172, 4) = 688 CTAs
    qlinear_s8_kernel<<<grid, THREADS>>>(qw);

    combine_kernel<<<MN / (THREADS * 4), THREADS>>>(scales, bias, out);  // 344 blocks
}

// round 9
// speedup vs baseline: 1.3311x; 1.0898x over previous
#include <cuda_runtime.h>
#include <cuda_fp16.h>
#include <stdint.h>

// Problem constants (fixed shapes from reference)
#define M_DIM 32
#define N_DIM 11008
#define K_DIM 4096

// Harness promotes unsupported dtypes: float16 -> float32, int8 -> int32.
// x fp32 [32,4096], qweight int32 [11008,4096], scales fp32 [11008],
// bias fp32 [11008], out fp32 [32,11008] (values fp16-rounded like reference).

#define N_TILE   64                 // output channels per CTA (11008 = 172 * 64)
#define SPLIT_K  4                  // K-splits -> grid (172, 4) = 688 CTAs
#define K_PER_SPLIT (K_DIM / SPLIT_K)      // 1024
#define K_CHUNK  64                 // K elements staged per pipeline stage
#define N_WARPS  8
#define THREADS  (N_WARPS * 32)
#define N_CHUNKS (K_PER_SPLIT / K_CHUNK)   // 16
#define KSTEPS   (K_CHUNK / 16)     // 4 mma k-steps per chunk

#define X_STRIDE 72                 // halves per x row in smem (64 + 8 pad; 144B, 16B-aligned rows)
#define W_STRIDE 72                 // int32 per w row in smem (64 + 8 pad)

#define MN (M_DIM * N_DIM)          // 352256

// fp32 split-K partials. Static device scratch (no allocation in kernel_launch).
__device__ float g_part[SPLIT_K * MN];   // 5.64 MB

__device__ __forceinline__ uint32_t smem_addr(const void* p) {
    return (uint32_t)__cvta_generic_to_shared(p);
}

// cp.async the weight tile for K-chunk starting at k0 into sw.
__device__ __forceinline__ void issue_w(
    const int32_t* __restrict__ qw, int n_base, int32_t* sw, int k0, int tid)
{
    // 64 rows x 64 int32 = 16 segs/row of 16 B -> 1024 segs, 4 per thread
    #pragma unroll
    for (int s = 0; s < 4; s++) {
        int seg = tid + s * THREADS;
        int row = seg >> 4;
        int col = seg & 15;
        const int32_t* src = qw + (size_t)(n_base + row) * K_DIM + k0 + col * 4;
        uint32_t dst = smem_addr(sw + row * W_STRIDE + col * 4);
        asm volatile("cp.async.cg.shared.global [%0], [%1], 16;\n" :: "r"(dst), "l"(src));
    }
    asm volatile("cp.async.commit_group;\n");
}

// Load this thread's 8 fp32 x values for chunk k0 (row tid/8, cols (tid%8)*8 .. +7).
__device__ __forceinline__ void ldg_x(
    const float* __restrict__ x32, int k0, int tid, float4& a, float4& b)
{
    const float* src = x32 + (size_t)(tid >> 3) * K_DIM + k0 + (tid & 7) * 8;
    a = __ldg((const float4*)src);
    b = __ldg((const float4*)(src + 4));
}

// Convert the 8 fp32 values to fp16 and store as one 16B STS to the x tile.
__device__ __forceinline__ void sts_x(__half* sx, int tid, float4 a, float4 b)
{
    __half2 h[4];
    h[0] = __halves2half2(__float2half(a.x), __float2half(a.y));
    h[1] = __halves2half2(__float2half(a.z), __float2half(a.w));
    h[2] = __halves2half2(__float2half(b.x), __float2half(b.y));
    h[3] = __halves2half2(__float2half(b.z), __float2half(b.w));
    *reinterpret_cast<uint4*>(sx + (tid >> 3) * X_STRIDE + (tid & 7) * 8) =
        *reinterpret_cast<uint4*>(h);
}

__global__ void __launch_bounds__(THREADS, 3)
qlinear_s8_kernel(const int32_t* __restrict__ qw, const float* __restrict__ x32)
{
    __shared__ __align__(16) __half   sx[2][M_DIM * X_STRIDE];   // 2 x 4608 B
    __shared__ __align__(16) int32_t  sw[2][N_TILE * W_STRIDE];  // 2 x 18432 B

    const int tid  = threadIdx.x;
    const int warp = tid >> 5;
    const int lane = tid & 31;
    const int n_base = blockIdx.x * N_TILE;
    const int split  = blockIdx.y;
    const int k_base = split * K_PER_SPLIT;

    float acc[2][4] = {{0.f, 0.f, 0.f, 0.f}, {0.f, 0.f, 0.f, 0.f}};

    // B operand per-thread source: row (n) = warp*8 + lane/4, k offset (lane%4)*2.
    const int o_row = warp * 8 + (lane >> 2);
    const int kb    = (lane & 3) * 2;

    // Prologue: stage chunk 0 (weights via cp.async, x via LDG->cvt->STS).
    issue_w(qw, n_base, sw[0], k_base, tid);
    {
        float4 xa, xb;
        ldg_x(x32, k_base, tid, xa, xb);
        sts_x(sx[0], tid, xa, xb);
    }

    for (int ch = 0; ch < N_CHUNKS; ch++) {
        const int buf = ch & 1;
        float4 xa, xb;
        const bool has_next = (ch + 1 < N_CHUNKS);

        if (has_next) {
            issue_w(qw, n_base, sw[buf ^ 1], k_base + (ch + 1) * K_CHUNK, tid);
            ldg_x(x32, k_base + (ch + 1) * K_CHUNK, tid, xa, xb);   // latency hidden by MMAs
            asm volatile("cp.async.wait_group 1;\n");
        } else {
            asm volatile("cp.async.wait_group 0;\n");
        }
        __syncthreads();   // (A) chunk `ch` tiles ready for everyone

        const __half*   xs = sx[buf];
        const int32_t*  ws = &sw[buf][o_row * W_STRIDE + kb];

        // ldmatrix base: lane -> row (lane%16), col block (lane/16)*8 halves.
        const uint32_t a_base = smem_addr(xs) +
            ((uint32_t)((lane & 15) * X_STRIDE + (lane >> 4) * 8) * 2u);

        #pragma unroll
        for (int ks = 0; ks < KSTEPS; ks++) {
            const int kl = ks * 16;

            uint32_t a0[4], a1[4];
            {
                uint32_t addr0 = a_base + (uint32_t)(kl * 2);
                asm volatile("ldmatrix.sync.aligned.m8n8.x4.shared.b16 {%0,%1,%2,%3}, [%4];\n"
                             : "=r"(a0[0]), "=r"(a0[1]), "=r"(a0[2]), "=r"(a0[3]) : "r"(addr0));
                uint32_t addr1 = addr0 + (uint32_t)(16 * X_STRIDE * 2);
                asm volatile("ldmatrix.sync.aligned.m8n8.x4.shared.b16 {%0,%1,%2,%3}, [%4];\n"
                             : "=r"(a1[0]), "=r"(a1[1]), "=r"(a1[2]), "=r"(a1[3]) : "r"(addr1));
            }

            // B fragment: int32 weight pairs -> half2 (exact for |v| <= 128)
            int2 w0 = *reinterpret_cast<const int2*>(ws + kl);
            int2 w1 = *reinterpret_cast<const int2*>(ws + kl + 8);
            __half2 b0h = __halves2half2(__int2half_rn(w0.x), __int2half_rn(w0.y));
            __half2 b1h = __halves2half2(__int2half_rn(w1.x), __int2half_rn(w1.y));
            uint32_t b0 = *reinterpret_cast<uint32_t*>(&b0h);
            uint32_t b1 = *reinterpret_cast<uint32_t*>(&b1h);

            asm volatile(
                "mma.sync.aligned.m16n8k16.row.col.f32.f16.f16.f32 "
                "{%0,%1,%2,%3}, {%4,%5,%6,%7}, {%8,%9}, {%0,%1,%2,%3};\n"
                : "+f"(acc[0][0]), "+f"(acc[0][1]), "+f"(acc[0][2]), "+f"(acc[0][3])
                : "r"(a0[0]), "r"(a0[1]), "r"(a0[2]), "r"(a0[3]), "r"(b0), "r"(b1));
            asm volatile(
                "mma.sync.aligned.m16n8k16.row.col.f32.f16.f16.f32 "
                "{%0,%1,%2,%3}, {%4,%5,%6,%7}, {%8,%9}, {%0,%1,%2,%3};\n"
                : "+f"(acc[1][0]), "+f"(acc[1][1]), "+f"(acc[1][2]), "+f"(acc[1][3])
                : "r"(a1[0]), "r"(a1[1]), "r"(a1[2]), "r"(a1[3]), "r"(b0), "r"(b1));
        }

        if (has_next) sts_x(sx[buf ^ 1], tid, xa, xb);   // stage next x tile
        __syncthreads();   // (B) compute on buf done; sts_x visible before next read
    }

    // Store raw fp32 partials (scale/bias applied in combine kernel).
    float* pbase = g_part + (size_t)split * MN;
    const int oc = n_base + warp * 8 + (lane & 3) * 2;

    #pragma unroll
    for (int mt = 0; mt < 2; mt++) {
        const int t0 = mt * 16 + (lane >> 2);
        *reinterpret_cast<float2*>(pbase + (size_t)t0 * N_DIM + oc) =
            make_float2(acc[mt][0], acc[mt][1]);
        *reinterpret_cast<float2*>(pbase + (size_t)(t0 + 8) * N_DIM + oc) =
            make_float2(acc[mt][2], acc[mt][3]);
    }
}

// Combine: out[t,o] = fp16_round((sum_s part[s,t,o]) * scale[o] + bias[o]) as fp32.
__global__ void __launch_bounds__(THREADS)
combine_kernel(const float* __restrict__ scales,
               const float* __restrict__ bias,
               float* __restrict__ out)
{
    const int i = (blockIdx.x * THREADS + threadIdx.x) * 4;   // element t*N+o, o % 4 == 0
    const int o = i % N_DIM;

    float4 p = *reinterpret_cast<const float4*>(g_part + i);
    #pragma unroll
    for (int s = 1; s < SPLIT_K; s++) {
        float4 q = *reinterpret_cast<const float4*>(g_part + (size_t)s * MN + i);
        p.x += q.x; p.y += q.y; p.z += q.z; p.w += q.w;
    }
    float4 sc = *reinterpret_cast<const float4*>(scales + o);
    float4 bz = *reinterpret_cast<const float4*>(bias + o);

    float4 v;
    v.x = __half2float(__float2half(p.x * sc.x + bz.x));
    v.y = __half2float(__float2half(p.y * sc.y + bz.y));
    v.z = __half2float(__float2half(p.z * sc.z + bz.z));
    v.w = __half2float(__float2half(p.w * sc.w + bz.w));
    *reinterpret_cast<float4*>(out + i) = v;
}

extern "C" void kernel_launch(void* const* d_in, const int* in_sizes, int n_in,
                              void* d_out, int out_size)
{
    const float*    x      = (const float*)d_in[0];
    const int32_t*  qw     = (const int32_t*)d_in[1];
    const float*    scales = (const float*)d_in[2];
    const float*    bias   = (const float*)d_in[3];
    float*          out    = (float*)d_out;

    dim3 grid(N_DIM / N_TILE, SPLIT_K);   // (172, 4) = 688 CTAs
    qlinear_s8_kernel<<<grid, THREADS>>>(qw, x);

    combine_kernel<<<MN / (THREADS * 4), THREADS>>>(scales, bias, out);  // 344 blocks
}